// round 10
// baseline (speedup 1.0000x reference)
#include <cuda_runtime.h>
#include <cuda_bf16.h>

#define LL 4
#define CC 128
#define HH 240
#define WW 480
#define PP (HH*WW)      // 115200
#define RR 8
#define KK 36
#define CH 64           // C/2
#define NW (CC*RR + RR*KK)  // 1312
#define MSPLIT 8        // mean partial splits per row
#define CSPLIT 2        // final kernel channel splits
#define CPB (CC/CSPLIT) // 64 channels per block

// Scratch (device globals; no allocation allowed)
__device__ float g_part[LL*CC*MSPLIT];
__device__ float g_h[LL*CH];
__device__ __align__(16) float g_W1[LL*CC*RR];   // gain-folded W1
__device__ float g_W2[LL*RR*KK];

// ---------------------------------------------------------------------------
// Kernel 1: partial sums over H*W.  grid = L*C*MSPLIT = 4096 blocks, 256 thr.
// ---------------------------------------------------------------------------
__global__ void mean_kernel(const float* __restrict__ x) {
    int row   = blockIdx.x >> 3;            // l*C + c
    int split = blockIdx.x & 7;
    const int n4 = PP / 4 / MSPLIT;         // 3600 float4 per split
    const float4* xr = (const float4*)(x + (size_t)row * PP) + split * n4;
    float s0 = 0.f, s1 = 0.f;
    int i = threadIdx.x;
    for (; i + 256 < n4; i += 512) {
        float4 a = xr[i];
        float4 b = xr[i + 256];
        s0 += (a.x + a.y) + (a.z + a.w);
        s1 += (b.x + b.y) + (b.z + b.w);
    }
    if (i < n4) {
        float4 a = xr[i];
        s0 += (a.x + a.y) + (a.z + a.w);
    }
    float s = s0 + s1;
    #pragma unroll
    for (int o = 16; o; o >>= 1) s += __shfl_xor_sync(0xffffffffu, s, o);
    __shared__ float red[8];
    int warp = threadIdx.x >> 5;
    if ((threadIdx.x & 31) == 0) red[warp] = s;
    __syncthreads();
    if (threadIdx.x == 0) {
        float t = 0.f;
        #pragma unroll
        for (int w = 0; w < 8; w++) t += red[w];
        g_part[row * MSPLIT + split] = t;
    }
}

// ---------------------------------------------------------------------------
// Kernel 2a: ctx reduce + first GEMM + silu.  One block, 256 threads.
// ---------------------------------------------------------------------------
__global__ void hyper1_kernel(const float* __restrict__ Wa, const float* __restrict__ ba) {
    __shared__ float ctx[LL*CC];
    int t = threadIdx.x;
    for (int i = t; i < LL*CC; i += 256) {
        float s = 0.f;
        #pragma unroll
        for (int m = 0; m < MSPLIT; m++) s += g_part[i*MSPLIT + m];
        ctx[i] = s * (1.0f / (float)PP);
    }
    __syncthreads();
    int l = t >> 6, j = t & 63;
    float acc = ba[j];
    #pragma unroll 16
    for (int i = 0; i < CC; i++) acc += ctx[l*CC + i] * Wa[i*CH + j];
    g_h[t] = acc / (1.0f + expf(-acc));   // silu
}

// ---------------------------------------------------------------------------
// Kernel 2b: second GEMM, parallel.  grid = ceil(L*NW/256) = 21 blocks.
// ---------------------------------------------------------------------------
__global__ void hyper2_kernel(const float* __restrict__ Wb, const float* __restrict__ bb,
                              const float* __restrict__ gain) {
    __shared__ float h[LL*CH];
    int t = threadIdx.x;
    if (t < LL*CH) h[t] = g_h[t];
    __syncthreads();
    int idx = blockIdx.x * 256 + t;
    if (idx >= LL*NW) return;
    int l = idx / NW, j = idx - l*NW;
    float acc = bb[j];
    #pragma unroll 16
    for (int i = 0; i < CH; i++) acc += h[l*CH + i] * Wb[i*NW + j];
    if (j < CC*RR) {
        int c = j >> 3, r = j & 7;
        g_W1[(l*CC + c)*RR + r] = gain[c] * acc;
    } else {
        g_W2[l*RR*KK + (j - CC*RR)] = acc;  // [l][r][k], r*KK+k
    }
}

// ---------------------------------------------------------------------------
// Kernel 3: fused z + bias-add, channel-split for occupancy.
//   z[r] = sum_k W2[l,r,k] * Y[k,p]        (per-thread, Y via L2)
//   out[l,c,p] = x[l,c,p] + sum_r W1g[l,c,r] * z[r]
// grid = (ceil(PP/4/256), L, CSPLIT), 256 threads; 4 pixels/thread (float4),
// CPB=64 channels per block.
// ---------------------------------------------------------------------------
__device__ __forceinline__ void fma4(float4& a, float w, const float4& z) {
    a.x = fmaf(w, z.x, a.x);
    a.y = fmaf(w, z.y, a.y);
    a.z = fmaf(w, z.z, a.z);
    a.w = fmaf(w, z.w, a.w);
}

__global__ __launch_bounds__(256) void final_kernel(const float* __restrict__ x,
                                                    const float* __restrict__ Y,
                                                    float* __restrict__ out) {
    int l  = blockIdx.y;
    int c0 = blockIdx.z * CPB;              // first channel for this block
    __shared__ float4 W1s[CPB*2];           // 128 float4 = [c][r0..3],[c][r4..7]
    __shared__ float  W2s[RR*KK];           // 288 entries — cover ALL of them
    int t = threadIdx.x;
    const float4* w1g = (const float4*)(g_W1 + (l*CC + c0)*RR);
    if (t < CPB*2) W1s[t] = w1g[t];
    for (int i = t; i < RR*KK; i += 256) W2s[i] = g_W2[l*RR*KK + i];
    __syncthreads();
    int p4 = blockIdx.x * 256 + t;
    if (p4 >= PP/4) return;

    // z[r] = sum_k W2[r,k] * Y[k, 4 pixels]
    float4 z[RR];
    #pragma unroll
    for (int r = 0; r < RR; r++) { z[r].x = z[r].y = z[r].z = z[r].w = 0.f; }
    const float4* Y4 = (const float4*)Y;
    #pragma unroll 4
    for (int k = 0; k < KK; k++) {
        float4 y = Y4[k*(PP/4) + p4];
        #pragma unroll
        for (int r = 0; r < RR; r++) fma4(z[r], W2s[r*KK + k], y);
    }

    const float4* x4 = (const float4*)x;
    float4* o4 = (float4*)out;
    size_t base = ((size_t)l * CC + c0) * (PP/4) + p4;
    #pragma unroll 8
    for (int c = 0; c < CPB; c++) {
        float4 a = x4[base + (size_t)c*(PP/4)];
        float4 w0 = W1s[c*2], w1 = W1s[c*2 + 1];
        fma4(a, w0.x, z[0]); fma4(a, w0.y, z[1]);
        fma4(a, w0.z, z[2]); fma4(a, w0.w, z[3]);
        fma4(a, w1.x, z[4]); fma4(a, w1.y, z[5]);
        fma4(a, w1.z, z[6]); fma4(a, w1.w, z[7]);
        o4[base + (size_t)c*(PP/4)] = a;
    }
}

// ---------------------------------------------------------------------------
extern "C" void kernel_launch(void* const* d_in, const int* in_sizes, int n_in,
                              void* d_out, int out_size) {
    const float* x    = (const float*)d_in[0];
    const float* Wa   = (const float*)d_in[1];
    const float* ba   = (const float*)d_in[2];
    const float* Wb   = (const float*)d_in[3];
    const float* bb   = (const float*)d_in[4];
    const float* gain = (const float*)d_in[5];
    const float* Y    = (const float*)d_in[6];
    float* out = (float*)d_out;

    mean_kernel<<<LL*CC*MSPLIT, 256>>>(x);
    hyper1_kernel<<<1, 256>>>(Wa, ba);
    hyper2_kernel<<<(LL*NW + 255)/256, 256>>>(Wb, bb, gain);
    dim3 g((PP/4 + 255)/256, LL, CSPLIT);
    final_kernel<<<g, 256>>>(x, Y, out);
}

// round 11
// speedup vs baseline: 1.0840x; 1.0840x over previous
#include <cuda_runtime.h>
#include <cuda_bf16.h>

#define LL 4
#define CC 128
#define HH 240
#define WW 480
#define PP (HH*WW)      // 115200
#define RR 8
#define KK 36
#define CH 64           // C/2
#define NW (CC*RR + RR*KK)  // 1312
#define MSPLIT 8        // mean partial splits per row

// Scratch (device globals; no allocation allowed)
__device__ float g_part[LL*CC*MSPLIT];
__device__ float g_h[LL*CH];
__device__ __align__(16) float g_W1[LL*CC*RR];   // gain-folded W1
__device__ float g_W2[LL*RR*KK];

// ---------------------------------------------------------------------------
// Kernel 1: partial sums over H*W.  grid = L*C*MSPLIT = 4096 blocks, 256 thr.
// ---------------------------------------------------------------------------
__global__ void mean_kernel(const float* __restrict__ x) {
    int row   = blockIdx.x >> 3;            // l*C + c
    int split = blockIdx.x & 7;
    const int n4 = PP / 4 / MSPLIT;         // 3600 float4 per split
    const float4* xr = (const float4*)(x + (size_t)row * PP) + split * n4;
    float s0 = 0.f, s1 = 0.f;
    int i = threadIdx.x;
    for (; i + 256 < n4; i += 512) {
        float4 a = xr[i];
        float4 b = xr[i + 256];
        s0 += (a.x + a.y) + (a.z + a.w);
        s1 += (b.x + b.y) + (b.z + b.w);
    }
    if (i < n4) {
        float4 a = xr[i];
        s0 += (a.x + a.y) + (a.z + a.w);
    }
    float s = s0 + s1;
    #pragma unroll
    for (int o = 16; o; o >>= 1) s += __shfl_xor_sync(0xffffffffu, s, o);
    __shared__ float red[8];
    int warp = threadIdx.x >> 5;
    if ((threadIdx.x & 31) == 0) red[warp] = s;
    __syncthreads();
    if (threadIdx.x == 0) {
        float t = 0.f;
        #pragma unroll
        for (int w = 0; w < 8; w++) t += red[w];
        g_part[row * MSPLIT + split] = t;
    }
}

// ---------------------------------------------------------------------------
// Kernel 2a: ctx reduce + first GEMM + silu.  One block, 256 threads.
// ---------------------------------------------------------------------------
__global__ void hyper1_kernel(const float* __restrict__ Wa, const float* __restrict__ ba) {
    __shared__ float ctx[LL*CC];
    int t = threadIdx.x;
    for (int i = t; i < LL*CC; i += 256) {
        float s = 0.f;
        #pragma unroll
        for (int m = 0; m < MSPLIT; m++) s += g_part[i*MSPLIT + m];
        ctx[i] = s * (1.0f / (float)PP);
    }
    __syncthreads();
    int l = t >> 6, j = t & 63;
    float acc = ba[j];
    #pragma unroll 16
    for (int i = 0; i < CC; i++) acc += ctx[l*CC + i] * Wa[i*CH + j];
    g_h[t] = acc / (1.0f + expf(-acc));   // silu
}

// ---------------------------------------------------------------------------
// Kernel 2b: second GEMM, parallel.  grid = ceil(L*NW/256) = 21 blocks.
// ---------------------------------------------------------------------------
__global__ void hyper2_kernel(const float* __restrict__ Wb, const float* __restrict__ bb,
                              const float* __restrict__ gain) {
    __shared__ float h[LL*CH];
    int t = threadIdx.x;
    if (t < LL*CH) h[t] = g_h[t];
    __syncthreads();
    int idx = blockIdx.x * 256 + t;
    if (idx >= LL*NW) return;
    int l = idx / NW, j = idx - l*NW;
    float acc = bb[j];
    #pragma unroll 16
    for (int i = 0; i < CH; i++) acc += h[l*CH + i] * Wb[i*NW + j];
    if (j < CC*RR) {
        int c = j >> 3, r = j & 7;
        g_W1[(l*CC + c)*RR + r] = gain[c] * acc;
    } else {
        g_W2[l*RR*KK + (j - CC*RR)] = acc;  // [l][r][k], r*KK+k
    }
}

// ---------------------------------------------------------------------------
// Kernel 3: fused z + bias-add.  2 pixels/thread (float2) for 2x warp count;
// __launch_bounds__(256,4) forces <=64 regs -> 4 blocks/SM -> 50% occupancy.
//   z[r] = sum_k W2[l,r,k] * Y[k,p]        (per-thread, Y via L2)
//   out[l,c,p] = x[l,c,p] + sum_r W1g[l,c,r] * z[r]
// grid = (PP/2/256 = 225, L), 256 threads.
// ---------------------------------------------------------------------------
__device__ __forceinline__ void fma2(float2& a, float w, const float2& z) {
    a.x = fmaf(w, z.x, a.x);
    a.y = fmaf(w, z.y, a.y);
}

__global__ __launch_bounds__(256, 4) void final_kernel(const float* __restrict__ x,
                                                       const float* __restrict__ Y,
                                                       float* __restrict__ out) {
    int l = blockIdx.y;
    __shared__ float4 W1s[CC*2];            // 256 float4 = [c][r0..3],[c][r4..7]
    __shared__ float  W2s[RR*KK];           // 288 entries — strided full cover
    int t = threadIdx.x;
    const float4* w1g = (const float4*)(g_W1 + l*CC*RR);
    W1s[t] = w1g[t];
    for (int i = t; i < RR*KK; i += 256) W2s[i] = g_W2[l*RR*KK + i];
    __syncthreads();
    int p2 = blockIdx.x * 256 + t;          // float2 index < PP/2

    // z[r] = sum_k W2[r,k] * Y[k, 2 pixels]
    float2 z[RR];
    #pragma unroll
    for (int r = 0; r < RR; r++) { z[r].x = 0.f; z[r].y = 0.f; }
    const float2* Y2 = (const float2*)Y;
    #pragma unroll 6
    for (int k = 0; k < KK; k++) {
        float2 y = Y2[k*(PP/2) + p2];
        #pragma unroll
        for (int r = 0; r < RR; r++) fma2(z[r], W2s[r*KK + k], y);
    }

    const float2* x2 = (const float2*)x;
    float2* o2 = (float2*)out;
    size_t base = (size_t)l * CC * (PP/2) + p2;
    #pragma unroll 8
    for (int c = 0; c < CC; c++) {
        float2 a = x2[base + (size_t)c*(PP/2)];
        float4 w0 = W1s[c*2], w1 = W1s[c*2 + 1];
        fma2(a, w0.x, z[0]); fma2(a, w0.y, z[1]);
        fma2(a, w0.z, z[2]); fma2(a, w0.w, z[3]);
        fma2(a, w1.x, z[4]); fma2(a, w1.y, z[5]);
        fma2(a, w1.z, z[6]); fma2(a, w1.w, z[7]);
        o2[base + (size_t)c*(PP/2)] = a;
    }
}

// ---------------------------------------------------------------------------
extern "C" void kernel_launch(void* const* d_in, const int* in_sizes, int n_in,
                              void* d_out, int out_size) {
    const float* x    = (const float*)d_in[0];
    const float* Wa   = (const float*)d_in[1];
    const float* ba   = (const float*)d_in[2];
    const float* Wb   = (const float*)d_in[3];
    const float* bb   = (const float*)d_in[4];
    const float* gain = (const float*)d_in[5];
    const float* Y    = (const float*)d_in[6];
    float* out = (float*)d_out;

    mean_kernel<<<LL*CC*MSPLIT, 256>>>(x);
    hyper1_kernel<<<1, 256>>>(Wa, ba);
    hyper2_kernel<<<(LL*NW + 255)/256, 256>>>(Wb, bb, gain);
    dim3 g(PP/2/256, LL);
    final_kernel<<<g, 256>>>(x, Y, out);
}

// round 14
// speedup vs baseline: 1.0969x; 1.0119x over previous
#include <cuda_runtime.h>
#include <cuda_bf16.h>

#define LL 4
#define CC 128
#define HH 240
#define WW 480
#define PP (HH*WW)      // 115200
#define RR 8
#define KK 36
#define CH 64           // C/2
#define NW (CC*RR + RR*KK)  // 1312
#define MSPLIT 8        // mean partial splits per row

// Scratch (device globals; no allocation allowed)
__device__ float g_part[LL*CC*MSPLIT];
__device__ float g_h[LL*CH];
__device__ __align__(16) float g_W1[LL*CC*RR];   // gain-folded W1
__device__ float g_W2[LL*RR*KK];
__device__ __align__(16) float g_Z[LL*RR*PP];    // 14.7 MB

// ---------------------------------------------------------------------------
// Kernel 1: partial sums over H*W.  grid = L*C*MSPLIT = 4096 blocks, 256 thr.
// ---------------------------------------------------------------------------
__global__ void mean_kernel(const float* __restrict__ x) {
    int row   = blockIdx.x >> 3;            // l*C + c
    int split = blockIdx.x & 7;
    const int n4 = PP / 4 / MSPLIT;         // 3600 float4 per split
    const float4* xr = (const float4*)(x + (size_t)row * PP) + split * n4;
    float s0 = 0.f, s1 = 0.f;
    int i = threadIdx.x;
    for (; i + 256 < n4; i += 512) {
        float4 a = xr[i];
        float4 b = xr[i + 256];
        s0 += (a.x + a.y) + (a.z + a.w);
        s1 += (b.x + b.y) + (b.z + b.w);
    }
    if (i < n4) {
        float4 a = xr[i];
        s0 += (a.x + a.y) + (a.z + a.w);
    }
    float s = s0 + s1;
    #pragma unroll
    for (int o = 16; o; o >>= 1) s += __shfl_xor_sync(0xffffffffu, s, o);
    __shared__ float red[8];
    int warp = threadIdx.x >> 5;
    if ((threadIdx.x & 31) == 0) red[warp] = s;
    __syncthreads();
    if (threadIdx.x == 0) {
        float t = 0.f;
        #pragma unroll
        for (int w = 0; w < 8; w++) t += red[w];
        g_part[row * MSPLIT + split] = t;
    }
}

// ---------------------------------------------------------------------------
// Kernel 2a: ctx reduce + first GEMM + silu.  One block, 256 threads.
// ---------------------------------------------------------------------------
__global__ void hyper1_kernel(const float* __restrict__ Wa, const float* __restrict__ ba) {
    __shared__ float ctx[LL*CC];
    int t = threadIdx.x;
    for (int i = t; i < LL*CC; i += 256) {
        float s = 0.f;
        #pragma unroll
        for (int m = 0; m < MSPLIT; m++) s += g_part[i*MSPLIT + m];
        ctx[i] = s * (1.0f / (float)PP);
    }
    __syncthreads();
    int l = t >> 6, j = t & 63;
    float acc = ba[j];
    #pragma unroll 16
    for (int i = 0; i < CC; i++) acc += ctx[l*CC + i] * Wa[i*CH + j];
    g_h[t] = acc / (1.0f + expf(-acc));   // silu
}

// ---------------------------------------------------------------------------
// Kernel 2b: second GEMM, parallel.  grid = ceil(L*NW/256) = 21 blocks.
// ---------------------------------------------------------------------------
__global__ void hyper2_kernel(const float* __restrict__ Wb, const float* __restrict__ bb,
                              const float* __restrict__ gain) {
    __shared__ float h[LL*CH];
    int t = threadIdx.x;
    if (t < LL*CH) h[t] = g_h[t];
    __syncthreads();
    int idx = blockIdx.x * 256 + t;
    if (idx >= LL*NW) return;
    int l = idx / NW, j = idx - l*NW;
    float acc = bb[j];
    #pragma unroll 16
    for (int i = 0; i < CH; i++) acc += h[l*CH + i] * Wb[i*NW + j];
    if (j < CC*RR) {
        int c = j >> 3, r = j & 7;
        g_W1[(l*CC + c)*RR + r] = gain[c] * acc;
    } else {
        g_W2[l*RR*KK + (j - CC*RR)] = acc;  // [l][r][k], r*KK+k
    }
}

// ---------------------------------------------------------------------------
// Kernel 3: Z[l,r,p] = sum_k W2[l,r,k] * Y[k,p].  One l per block:
// 8 float2 accumulators -> low regs, high occupancy.
// grid = (PP/2/256 = 225, LL) = 900 blocks, 256 threads.  Y re-read per l (L2).
// ---------------------------------------------------------------------------
__global__ __launch_bounds__(256) void z_kernel(const float* __restrict__ Y) {
    int l = blockIdx.y;
    __shared__ float W2s[RR*KK];
    int t = threadIdx.x;
    for (int i = t; i < RR*KK; i += 256) W2s[i] = g_W2[l*RR*KK + i];
    __syncthreads();
    int p2 = blockIdx.x * 256 + t;          // float2 index < PP/2
    const float2* Y2 = (const float2*)Y;
    float2 acc[RR];
    #pragma unroll
    for (int r = 0; r < RR; r++) { acc[r].x = 0.f; acc[r].y = 0.f; }
    for (int k = 0; k < KK; k++) {
        float2 y = Y2[k*(PP/2) + p2];
        #pragma unroll
        for (int r = 0; r < RR; r++) {
            float w = W2s[r*KK + k];
            acc[r].x = fmaf(w, y.x, acc[r].x);
            acc[r].y = fmaf(w, y.y, acc[r].y);
        }
    }
    float2* Z2 = (float2*)g_Z;
    #pragma unroll
    for (int r = 0; r < RR; r++) Z2[(l*RR + r)*(PP/2) + p2] = acc[r];
}

// ---------------------------------------------------------------------------
// Kernel 4: out[l,c,p] = x[l,c,p] + sum_r W1g[l,c,r] * Z[l,r,p]
// 128-thread blocks for wave granularity: grid = (225, L) = 900 blocks,
// ~6 blocks/SM.  4 pixels/thread (float4).
// ---------------------------------------------------------------------------
__device__ __forceinline__ void fma4(float4& a, float w, const float4& z) {
    a.x = fmaf(w, z.x, a.x);
    a.y = fmaf(w, z.y, a.y);
    a.z = fmaf(w, z.z, a.z);
    a.w = fmaf(w, z.w, a.w);
}

__global__ __launch_bounds__(128) void final_kernel(const float* __restrict__ x,
                                                    float* __restrict__ out) {
    int l = blockIdx.y;
    __shared__ float4 W1s[CC*2];            // 256 float4 = [c][r0..3],[c][r4..7]
    int t = threadIdx.x;
    const float4* w1g = (const float4*)(g_W1 + l*CC*RR);
    W1s[t] = w1g[t];
    W1s[t + 128] = w1g[t + 128];
    __syncthreads();
    int p4 = blockIdx.x * 128 + t;          // float4 index < PP/4 (=28800, exact)
    float4 z[RR];
    const float4* Z4 = (const float4*)g_Z;
    #pragma unroll
    for (int r = 0; r < RR; r++) z[r] = Z4[(l*RR + r)*(PP/4) + p4];
    const float4* x4 = (const float4*)x;
    float4* o4 = (float4*)out;
    size_t base = (size_t)l * CC * (PP/4) + p4;
    #pragma unroll 8
    for (int c = 0; c < CC; c++) {
        float4 a = x4[base + (size_t)c*(PP/4)];
        float4 w0 = W1s[c*2], w1 = W1s[c*2 + 1];
        fma4(a, w0.x, z[0]); fma4(a, w0.y, z[1]);
        fma4(a, w0.z, z[2]); fma4(a, w0.w, z[3]);
        fma4(a, w1.x, z[4]); fma4(a, w1.y, z[5]);
        fma4(a, w1.z, z[6]); fma4(a, w1.w, z[7]);
        o4[base + (size_t)c*(PP/4)] = a;
    }
}

// ---------------------------------------------------------------------------
extern "C" void kernel_launch(void* const* d_in, const int* in_sizes, int n_in,
                              void* d_out, int out_size) {
    const float* x    = (const float*)d_in[0];
    const float* Wa   = (const float*)d_in[1];
    const float* ba   = (const float*)d_in[2];
    const float* Wb   = (const float*)d_in[3];
    const float* bb   = (const float*)d_in[4];
    const float* gain = (const float*)d_in[5];
    const float* Y    = (const float*)d_in[6];
    float* out = (float*)d_out;

    mean_kernel<<<LL*CC*MSPLIT, 256>>>(x);
    hyper1_kernel<<<1, 256>>>(Wa, ba);
    hyper2_kernel<<<(LL*NW + 255)/256, 256>>>(Wb, bb, gain);
    dim3 gz(PP/2/256, LL);
    z_kernel<<<gz, 256>>>(Y);
    dim3 gf(PP/4/128, LL);
    final_kernel<<<gf, 128>>>(x, out);
}

// round 15
// speedup vs baseline: 1.1275x; 1.0279x over previous
#include <cuda_runtime.h>
#include <cuda_bf16.h>

#define LL 4
#define CC 128
#define HH 240
#define WW 480
#define PP (HH*WW)      // 115200
#define RR 8
#define KK 36
#define CH 64           // C/2
#define NW (CC*RR + RR*KK)  // 1312
#define MSPLIT 8        // mean partial splits per row

// Scratch (device globals; no allocation allowed)
__device__ float g_part[LL*CC*MSPLIT];
__device__ float g_h[LL*CH];
__device__ __align__(16) float g_W1[LL*CC*RR];   // gain-folded W1
__device__ float g_W2[LL*RR*KK];
__device__ __align__(16) float g_Z[LL*RR*PP];    // 14.7 MB

// ---------------------------------------------------------------------------
// Kernel 1: partial sums over H*W.  grid = L*C*MSPLIT = 4096 blocks, 256 thr.
// ---------------------------------------------------------------------------
__global__ void mean_kernel(const float* __restrict__ x) {
    int row   = blockIdx.x >> 3;            // l*C + c
    int split = blockIdx.x & 7;
    const int n4 = PP / 4 / MSPLIT;         // 3600 float4 per split
    const float4* xr = (const float4*)(x + (size_t)row * PP) + split * n4;
    float s0 = 0.f, s1 = 0.f;
    int i = threadIdx.x;
    for (; i + 256 < n4; i += 512) {
        float4 a = xr[i];
        float4 b = xr[i + 256];
        s0 += (a.x + a.y) + (a.z + a.w);
        s1 += (b.x + b.y) + (b.z + b.w);
    }
    if (i < n4) {
        float4 a = xr[i];
        s0 += (a.x + a.y) + (a.z + a.w);
    }
    float s = s0 + s1;
    #pragma unroll
    for (int o = 16; o; o >>= 1) s += __shfl_xor_sync(0xffffffffu, s, o);
    __shared__ float red[8];
    int warp = threadIdx.x >> 5;
    if ((threadIdx.x & 31) == 0) red[warp] = s;
    __syncthreads();
    if (threadIdx.x == 0) {
        float t = 0.f;
        #pragma unroll
        for (int w = 0; w < 8; w++) t += red[w];
        g_part[row * MSPLIT + split] = t;
    }
}

// ---------------------------------------------------------------------------
// Kernel 2a: ctx reduce + first GEMM + silu.  One block, 256 threads.
// ---------------------------------------------------------------------------
__global__ void hyper1_kernel(const float* __restrict__ Wa, const float* __restrict__ ba) {
    __shared__ float ctx[LL*CC];
    int t = threadIdx.x;
    for (int i = t; i < LL*CC; i += 256) {
        float s = 0.f;
        #pragma unroll
        for (int m = 0; m < MSPLIT; m++) s += g_part[i*MSPLIT + m];
        ctx[i] = s * (1.0f / (float)PP);
    }
    __syncthreads();
    int l = t >> 6, j = t & 63;
    float acc = ba[j];
    #pragma unroll 16
    for (int i = 0; i < CC; i++) acc += ctx[l*CC + i] * Wa[i*CH + j];
    g_h[t] = acc / (1.0f + expf(-acc));   // silu
}

// ---------------------------------------------------------------------------
// Kernel 2b: second GEMM, parallel.  grid = ceil(L*NW/256) = 21 blocks.
// ---------------------------------------------------------------------------
__global__ void hyper2_kernel(const float* __restrict__ Wb, const float* __restrict__ bb,
                              const float* __restrict__ gain) {
    __shared__ float h[LL*CH];
    int t = threadIdx.x;
    if (t < LL*CH) h[t] = g_h[t];
    __syncthreads();
    int idx = blockIdx.x * 256 + t;
    if (idx >= LL*NW) return;
    int l = idx / NW, j = idx - l*NW;
    float acc = bb[j];
    #pragma unroll 16
    for (int i = 0; i < CH; i++) acc += h[l*CH + i] * Wb[i*NW + j];
    if (j < CC*RR) {
        int c = j >> 3, r = j & 7;
        g_W1[(l*CC + c)*RR + r] = gain[c] * acc;
    } else {
        g_W2[l*RR*KK + (j - CC*RR)] = acc;  // [l][r][k], r*KK+k
    }
}

// ---------------------------------------------------------------------------
// Kernel 3: Z[l,r,p] = sum_k W2[l,r,k] * Y[k,p].
// float4 pixels, one l per block.  grid = (225, LL), 128 threads:
// 225*128 = 28800 = PP/4 exact.  8 float4 accumulators (~48 regs).
// ---------------------------------------------------------------------------
__device__ __forceinline__ void fma4(float4& a, float w, const float4& z) {
    a.x = fmaf(w, z.x, a.x);
    a.y = fmaf(w, z.y, a.y);
    a.z = fmaf(w, z.z, a.z);
    a.w = fmaf(w, z.w, a.w);
}

__global__ __launch_bounds__(128) void z_kernel(const float* __restrict__ Y) {
    int l = blockIdx.y;
    __shared__ float W2s[RR*KK];
    int t = threadIdx.x;
    for (int i = t; i < RR*KK; i += 128) W2s[i] = g_W2[l*RR*KK + i];
    __syncthreads();
    int p4 = blockIdx.x * 128 + t;          // float4 index < PP/4 (exact)
    const float4* Y4 = (const float4*)Y;
    float4 acc[RR];
    #pragma unroll
    for (int r = 0; r < RR; r++) { acc[r].x = acc[r].y = acc[r].z = acc[r].w = 0.f; }
    #pragma unroll 2
    for (int k = 0; k < KK; k++) {
        float4 y = Y4[k*(PP/4) + p4];
        #pragma unroll
        for (int r = 0; r < RR; r++) fma4(acc[r], W2s[r*KK + k], y);
    }
    float4* Z4 = (float4*)g_Z;
    #pragma unroll
    for (int r = 0; r < RR; r++) Z4[(l*RR + r)*(PP/4) + p4] = acc[r];
}

// ---------------------------------------------------------------------------
// Kernel 4: out[l,c,p] = x[l,c,p] + sum_r W1g[l,c,r] * Z[l,r,p]
// Exact R5 config (best measured: 71.8us @ 76.8% DRAM):
// 256 threads, grid (113, L), 4 pixels/thread (float4), c-loop unroll 8.
// ---------------------------------------------------------------------------
__global__ __launch_bounds__(256) void final_kernel(const float* __restrict__ x,
                                                    float* __restrict__ out) {
    int l = blockIdx.y;
    __shared__ float4 W1s[CC*2];            // 256 float4 = [c][r0..3],[c][r4..7]
    int t = threadIdx.x;
    const float4* w1g = (const float4*)(g_W1 + l*CC*RR);
    W1s[t] = w1g[t];
    __syncthreads();
    int p4 = blockIdx.x * 256 + t;
    if (p4 >= PP/4) return;
    float4 z[RR];
    const float4* Z4 = (const float4*)g_Z;
    #pragma unroll
    for (int r = 0; r < RR; r++) z[r] = Z4[(l*RR + r)*(PP/4) + p4];
    const float4* x4 = (const float4*)x;
    float4* o4 = (float4*)out;
    size_t base = (size_t)l * CC * (PP/4) + p4;
    #pragma unroll 8
    for (int c = 0; c < CC; c++) {
        float4 a = x4[base + (size_t)c*(PP/4)];
        float4 w0 = W1s[c*2], w1 = W1s[c*2 + 1];
        fma4(a, w0.x, z[0]); fma4(a, w0.y, z[1]);
        fma4(a, w0.z, z[2]); fma4(a, w0.w, z[3]);
        fma4(a, w1.x, z[4]); fma4(a, w1.y, z[5]);
        fma4(a, w1.z, z[6]); fma4(a, w1.w, z[7]);
        o4[base + (size_t)c*(PP/4)] = a;
    }
}

// ---------------------------------------------------------------------------
extern "C" void kernel_launch(void* const* d_in, const int* in_sizes, int n_in,
                              void* d_out, int out_size) {
    const float* x    = (const float*)d_in[0];
    const float* Wa   = (const float*)d_in[1];
    const float* ba   = (const float*)d_in[2];
    const float* Wb   = (const float*)d_in[3];
    const float* bb   = (const float*)d_in[4];
    const float* gain = (const float*)d_in[5];
    const float* Y    = (const float*)d_in[6];
    float* out = (float*)d_out;

    mean_kernel<<<LL*CC*MSPLIT, 256>>>(x);
    hyper1_kernel<<<1, 256>>>(Wa, ba);
    hyper2_kernel<<<(LL*NW + 255)/256, 256>>>(Wb, bb, gain);
    dim3 gz(PP/4/128, LL);
    z_kernel<<<gz, 128>>>(Y);
    dim3 gf((PP/4 + 255)/256, LL);
    final_kernel<<<gf, 256>>>(x, out);
}